// round 7
// baseline (speedup 1.0000x reference)
#include <cuda_runtime.h>
#include <math.h>

#define N_NODES 50000
#define N_EDGES 800000
#define NUM_GRAPHS 64
#define IN_F 128
#define HID_F 256
#define OUT_F 256

#define SCAN_B 1024
#define SCAN_NBLK ((N_NODES + SCAN_B - 1) / SCAN_B)   // 49

// ---------------- scratch (static device globals) ----------------
__device__ int   g_degi[N_NODES];
__device__ int   g_row[N_NODES];
__device__ int   g_rowtmp[N_NODES];
__device__ int   g_cursor[N_NODES];
__device__ int   g_bsum[SCAN_NBLK];
__device__ int   g_boff[SCAN_NBLK];
__device__ __align__(8) int2 g_cpair[N_EDGES];   // {src, __float_as_int(norm)}
__device__ float g_dinv[N_NODES];
__device__ float g_sacc[N_NODES];
__device__ float g_s[N_NODES];
__device__ float g_t[N_NODES];
__device__ __align__(16) float g_yA[(size_t)N_NODES * IN_F];
__device__ __align__(16) float g_yB[(size_t)N_NODES * IN_F];
__device__ float g_T1[IN_F * HID_F];
__device__ float g_M[IN_F * OUT_F];
__device__ float g_u1[HID_F];
__device__ float g_u[OUT_F];
__device__ float g_w[OUT_F];
__device__ unsigned g_pmax[NUM_GRAPHS * OUT_F];
__device__ float g_psum[NUM_GRAPHS * OUT_F];
__device__ float g_cnt[NUM_GRAPHS];

// ---------------- helpers ----------------
__device__ __forceinline__ unsigned enc_f32(float f) {
    unsigned u = __float_as_uint(f);
    return (u & 0x80000000u) ? ~u : (u | 0x80000000u);
}
__device__ __forceinline__ float dec_f32(unsigned u) {
    return (u & 0x80000000u) ? __uint_as_float(u & 0x7FFFFFFFu) : __uint_as_float(~u);
}
// packed f32x2 (sm_100+): d = a*b + d (exact fp32 FMA per lane)
__device__ __forceinline__ void fma2(unsigned long long& d, unsigned long long a,
                                     unsigned long long b) {
    asm("fma.rn.f32x2 %0, %1, %2, %0;" : "+l"(d) : "l"(a), "l"(b));
}
__device__ __forceinline__ unsigned long long dup2(float v) {
    unsigned long long d;
    asm("mov.b64 %0, {%1, %1};" : "=l"(d) : "f"(v));
    return d;
}
__device__ __forceinline__ float2 unpk(unsigned long long v) {
    float2 r;
    asm("mov.b64 {%0, %1}, %2;" : "=f"(r.x), "=f"(r.y) : "l"(v));
    return r;
}

// ---------------- init (merged) ----------------
__global__ void k_init() {
    int i = blockIdx.x * blockDim.x + threadIdx.x;
    if (i < N_NODES) {
        g_degi[i] = 0;
        g_cursor[i] = 0;
        g_sacc[i] = 0.0f;
    }
    if (i < NUM_GRAPHS * OUT_F) {
        g_pmax[i] = 0x007FFFFFu;  // enc(-inf)
        g_psum[i] = 0.0f;
    }
    if (i < NUM_GRAPHS) g_cnt[i] = 0.0f;
}

// ---------------- CSR build (edge_index int32, layout [2, E]) ----------------
__global__ void k_deg(const int* __restrict__ ei) {
    int e = blockIdx.x * blockDim.x + threadIdx.x;
    if (e < N_EDGES) atomicAdd(&g_degi[ei[N_EDGES + e]], 1);
}

__global__ void k_scan1() {
    __shared__ int sm[SCAN_B];
    int t = threadIdx.x;
    int i = blockIdx.x * SCAN_B + t;
    int v = (i < N_NODES) ? g_degi[i] : 0;
    sm[t] = v;
    __syncthreads();
#pragma unroll
    for (int off = 1; off < SCAN_B; off <<= 1) {
        int a = (t >= off) ? sm[t - off] : 0;
        __syncthreads();
        sm[t] += a;
        __syncthreads();
    }
    if (i < N_NODES) g_rowtmp[i] = sm[t] - v;
    if (t == SCAN_B - 1) g_bsum[blockIdx.x] = sm[t];
}

__global__ void k_scan2() {
    if (threadIdx.x == 0) {
        int run = 0;
        for (int b = 0; b < SCAN_NBLK; b++) { g_boff[b] = run; run += g_bsum[b]; }
    }
}

// scan3 + dinv fused
__global__ void k_scan3() {
    int i = blockIdx.x * blockDim.x + threadIdx.x;
    if (i < N_NODES) {
        g_row[i] = g_rowtmp[i] + g_boff[i >> 10];
        g_dinv[i] = rsqrtf((float)(g_degi[i] + 1));
    }
}

// fill CSR pairs + accumulate s (sum of incoming norms)
__global__ void k_fill(const int* __restrict__ ei) {
    int e = blockIdx.x * blockDim.x + threadIdx.x;
    if (e < N_EDGES) {
        int s = ei[e];
        int d = ei[N_EDGES + e];
        float w = g_dinv[s] * g_dinv[d];
        int pos = g_row[d] + atomicAdd(&g_cursor[d], 1);
        g_cpair[pos] = make_int2(s, __float_as_int(w));
        atomicAdd(&g_sacc[d], w);
    }
}

// finalize s + per-graph node counts
__global__ void k_sfin_cnt(const int* __restrict__ batch) {
    int i = blockIdx.x * blockDim.x + threadIdx.x;
    if (i < N_NODES) {
        float di = g_dinv[i];
        g_s[i] = g_sacc[i] + di * di;
        atomicAdd(&g_cnt[batch[i]], 1.0f);
    }
}

__global__ void k_t() {
    int i = blockIdx.x * blockDim.x + threadIdx.x;
    if (i >= N_NODES) return;
    int beg = g_row[i], end = beg + g_degi[i];
    float acc = 0.f;
    for (int k = beg; k < end; k++) {
        int2 p = g_cpair[k];
        acc += __int_as_float(p.y) * g_s[p.x];
    }
    float di = g_dinv[i];
    g_t[i] = acc + di * di * g_s[i];
}

// ---------------- aggregation (gather): yout = A(yin), width 128 ----------------
// pass 0: x -> yA, pass 1: yA -> yB, pass 2: yB -> yA. One warp per dst node.
__global__ void __launch_bounds__(256) k_agg(const float* __restrict__ x, int pass) {
    const float* yin = pass == 0 ? x : (pass == 1 ? g_yA : g_yB);
    float* yout = pass == 1 ? g_yB : g_yA;
    int node = (blockIdx.x * blockDim.x + threadIdx.x) >> 5;
    int lane = threadIdx.x & 31;
    if (node >= N_NODES) return;
    int beg = g_row[node], end = beg + g_degi[node];
    float di = g_dinv[node];
    float d2 = di * di;

    float4 self = *((const float4*)(yin + (size_t)node * IN_F) + lane);
    float4 a0 = make_float4(d2 * self.x, d2 * self.y, d2 * self.z, d2 * self.w);
    float4 a1 = make_float4(0.f, 0.f, 0.f, 0.f);
    float4 a2 = make_float4(0.f, 0.f, 0.f, 0.f);
    float4 a3 = make_float4(0.f, 0.f, 0.f, 0.f);

    int k = beg;
    for (; k + 3 < end; k += 4) {
        int2 p0 = g_cpair[k];
        int2 p1 = g_cpair[k + 1];
        int2 p2 = g_cpair[k + 2];
        int2 p3 = g_cpair[k + 3];
        float n0 = __int_as_float(p0.y), n1 = __int_as_float(p1.y);
        float n2 = __int_as_float(p2.y), n3 = __int_as_float(p3.y);
        float4 v0 = *((const float4*)(yin + (size_t)p0.x * IN_F) + lane);
        float4 v1 = *((const float4*)(yin + (size_t)p1.x * IN_F) + lane);
        float4 v2 = *((const float4*)(yin + (size_t)p2.x * IN_F) + lane);
        float4 v3 = *((const float4*)(yin + (size_t)p3.x * IN_F) + lane);
        a0.x += n0 * v0.x; a0.y += n0 * v0.y; a0.z += n0 * v0.z; a0.w += n0 * v0.w;
        a1.x += n1 * v1.x; a1.y += n1 * v1.y; a1.z += n1 * v1.z; a1.w += n1 * v1.w;
        a2.x += n2 * v2.x; a2.y += n2 * v2.y; a2.z += n2 * v2.z; a2.w += n2 * v2.w;
        a3.x += n3 * v3.x; a3.y += n3 * v3.y; a3.z += n3 * v3.z; a3.w += n3 * v3.w;
    }
    for (; k < end; k++) {
        int2 p0 = g_cpair[k];
        float n0 = __int_as_float(p0.y);
        float4 v0 = *((const float4*)(yin + (size_t)p0.x * IN_F) + lane);
        a0.x += n0 * v0.x; a0.y += n0 * v0.y; a0.z += n0 * v0.z; a0.w += n0 * v0.w;
    }
    a0.x += a1.x + a2.x + a3.x;
    a0.y += a1.y + a2.y + a3.y;
    a0.z += a1.z + a2.z + a3.z;
    a0.w += a1.w + a2.w + a3.w;
    *((float4*)(yout + (size_t)node * IN_F) + lane) = a0;
}

// ---------------- small weight products ----------------
__global__ void k_wprod1(const float* __restrict__ W1, const float* __restrict__ W2,
                         const float* __restrict__ b1) {
    int j = threadIdx.x;
    int i = blockIdx.x;
    if (i < IN_F) {
        float acc = 0.f;
        for (int k = 0; k < HID_F; k++) acc += W1[i * HID_F + k] * W2[k * HID_F + j];
        g_T1[i * HID_F + j] = acc;
    } else {
        float acc = 0.f;
        for (int k = 0; k < HID_F; k++) acc += b1[k] * W2[k * HID_F + j];
        g_u1[j] = acc;
    }
}

__global__ void k_wprod2(const float* __restrict__ W3, const float* __restrict__ b2) {
    int j = threadIdx.x;
    int i = blockIdx.x;
    if (i < IN_F) {
        float acc = 0.f;
        for (int k = 0; k < HID_F; k++) acc += g_T1[i * HID_F + k] * W3[k * OUT_F + j];
        g_M[i * OUT_F + j] = acc;
    } else {
        float a = 0.f, b = 0.f;
        for (int k = 0; k < HID_F; k++) {
            float w3 = W3[k * OUT_F + j];
            a += g_u1[k] * w3;
            b += b2[k] * w3;
        }
        g_u[j] = a;
        g_w[j] = b;
    }
}

// ---------------- fused GEMM + pooling (f32x2 packed math) ----------------
// h = y3 @ M + t*u^T + s*w^T + b3, pooled directly into g_pmax / g_psum.
// Per-thread tile: rows ty*8+i (i=0..7), cols 2*tx + 32*jp + {0,1} (jp=0..3).
#define BM 128
#define BN 128
#define BK 32
__global__ void __launch_bounds__(256) k_gemm_pool(const float* __restrict__ b3,
                                                   const int* __restrict__ batch) {
    __shared__ __align__(16) float AsD[BK][2 * BM];   // duplicated A values, k-major
    __shared__ __align__(16) float Bs[BK][BN];        // B tile, k-major rows
    const float* A = g_yA;   // y3 lives in g_yA after 3 passes
    const float* B = g_M;
    int bx = blockIdx.y;
    int row0 = blockIdx.x * BM;
    int tid = threadIdx.x;
    int tx = tid & 15, ty = tid >> 4;

    unsigned long long acc2[8][4];
#pragma unroll
    for (int i = 0; i < 8; i++)
#pragma unroll
        for (int jp = 0; jp < 4; jp++) acc2[i][jp] = 0ull;

    for (int kb = 0; kb < IN_F; kb += BK) {
        // A tile: load float4 (node r, k-cols c..c+3), store duplicated k-major
#pragma unroll
        for (int i = 0; i < 4; i++) {
            int id = tid + i * 256;
            int r = id >> 3;            // node within tile (0..127)
            int c = (id & 7) * 4;       // k offset (0..28 step 4)
            float4 v = make_float4(0.f, 0.f, 0.f, 0.f);
            int gr = row0 + r;
            if (gr < N_NODES) v = *(const float4*)(A + (size_t)gr * IN_F + kb + c);
            *(unsigned long long*)&AsD[c + 0][2 * r] = dup2(v.x);
            *(unsigned long long*)&AsD[c + 1][2 * r] = dup2(v.y);
            *(unsigned long long*)&AsD[c + 2][2 * r] = dup2(v.z);
            *(unsigned long long*)&AsD[c + 3][2 * r] = dup2(v.w);
        }
        // B tile: k-major rows, plain
#pragma unroll
        for (int i = 0; i < 4; i++) {
            int id = tid + i * 256;
            int kr = id >> 5;
            int c = (id & 31) * 4;
            float4 v = *(const float4*)(B + (size_t)(kb + kr) * OUT_F + bx * BN + c);
            *(float4*)&Bs[kr][c] = v;
        }
        __syncthreads();
#pragma unroll
        for (int k = 0; k < BK; k++) {
            unsigned long long ad[8], bb[4];
#pragma unroll
            for (int i = 0; i < 8; i++)
                ad[i] = *(const unsigned long long*)&AsD[k][2 * (ty * 8 + i)];
#pragma unroll
            for (int jp = 0; jp < 4; jp++)
                bb[jp] = *(const unsigned long long*)&Bs[k][2 * tx + 32 * jp];
#pragma unroll
            for (int i = 0; i < 8; i++)
#pragma unroll
                for (int jp = 0; jp < 4; jp++) fma2(acc2[i][jp], ad[i], bb[jp]);
        }
        __syncthreads();
    }

    // epilogue: rank-1 terms + bias, then pooled reduction (batch is sorted)
    float uj[4][2], wj[4][2], bj[4][2];
#pragma unroll
    for (int jp = 0; jp < 4; jp++)
#pragma unroll
        for (int h = 0; h < 2; h++) {
            int gc = bx * BN + 32 * jp + 2 * tx + h;
            uj[jp][h] = g_u[gc];
            wj[jp][h] = g_w[gc];
            bj[jp][h] = b3[gc];
        }

    int curg = -1;
    float rmax[4][2], rsum[4][2];
#pragma unroll
    for (int i = 0; i < 8; i++) {
        int gr = row0 + ty * 8 + i;
        if (gr < N_NODES) {
            int g = batch[gr];
            float tr = g_t[gr], sr = g_s[gr];
            if (g != curg) {
                if (curg >= 0) {
#pragma unroll
                    for (int jp = 0; jp < 4; jp++)
#pragma unroll
                        for (int h = 0; h < 2; h++) {
                            int gc = bx * BN + 32 * jp + 2 * tx + h;
                            atomicMax(&g_pmax[curg * OUT_F + gc], enc_f32(rmax[jp][h]));
                            atomicAdd(&g_psum[curg * OUT_F + gc], rsum[jp][h]);
                        }
                }
                curg = g;
#pragma unroll
                for (int jp = 0; jp < 4; jp++)
#pragma unroll
                    for (int h = 0; h < 2; h++) { rmax[jp][h] = -INFINITY; rsum[jp][h] = 0.f; }
            }
#pragma unroll
            for (int jp = 0; jp < 4; jp++) {
                float2 av = unpk(acc2[i][jp]);
                float hv0 = av.x + tr * uj[jp][0] + sr * wj[jp][0] + bj[jp][0];
                float hv1 = av.y + tr * uj[jp][1] + sr * wj[jp][1] + bj[jp][1];
                rmax[jp][0] = fmaxf(rmax[jp][0], hv0);
                rmax[jp][1] = fmaxf(rmax[jp][1], hv1);
                rsum[jp][0] += hv0;
                rsum[jp][1] += hv1;
            }
        }
    }
    if (curg >= 0) {
#pragma unroll
        for (int jp = 0; jp < 4; jp++)
#pragma unroll
            for (int h = 0; h < 2; h++) {
                int gc = bx * BN + 32 * jp + 2 * tx + h;
                atomicMax(&g_pmax[curg * OUT_F + gc], enc_f32(rmax[jp][h]));
                atomicAdd(&g_psum[curg * OUT_F + gc], rsum[jp][h]);
            }
    }
}

__global__ void k_out(float* __restrict__ out) {
    int g = blockIdx.x;
    int c = threadIdx.x;                   // 512 threads
    if (c < OUT_F) {
        out[g * 2 * OUT_F + c] = dec_f32(g_pmax[g * OUT_F + c]);
    } else {
        int cc = c - OUT_F;
        float cnt = g_cnt[g];
        out[g * 2 * OUT_F + OUT_F + cc] = g_psum[g * OUT_F + cc] / fmaxf(cnt, 1.0f);
    }
}

// ---------------- launch ----------------
extern "C" void kernel_launch(void* const* d_in, const int* in_sizes, int n_in,
                              void* d_out, int out_size) {
    const float* x = (const float*)d_in[0];
    const int* ei = (const int*)d_in[1];       // int32 (JAX x64 disabled)
    const int* batch = (const int*)d_in[2];    // int32
    const float* W1 = (const float*)d_in[3];
    const float* b1 = (const float*)d_in[4];
    const float* W2 = (const float*)d_in[5];
    const float* b2 = (const float*)d_in[6];
    const float* W3 = (const float*)d_in[7];
    const float* b3 = (const float*)d_in[8];
    float* out = (float*)d_out;

    const int NT = 256;
    int nb_nodes = (N_NODES + NT - 1) / NT;
    int nb_edges = (N_EDGES + NT - 1) / NT;
    int nb_aggw  = (N_NODES * 32 + NT - 1) / NT;     // one warp per node

    // CSR build
    k_init<<<nb_nodes, NT>>>();
    k_deg<<<nb_edges, NT>>>(ei);
    k_scan1<<<SCAN_NBLK, SCAN_B>>>();
    k_scan2<<<1, 32>>>();
    k_scan3<<<nb_nodes, NT>>>();
    k_fill<<<nb_edges, NT>>>(ei);

    // scalar propagations
    k_sfin_cnt<<<nb_nodes, NT>>>(batch);
    k_t<<<nb_nodes, NT>>>();

    // three aggregation passes at width 128 (gather, no feature atomics)
    k_agg<<<nb_aggw, NT>>>(x, 0);
    k_agg<<<nb_aggw, NT>>>(x, 1);
    k_agg<<<nb_aggw, NT>>>(x, 2);

    // weight pre-products (tiny)
    k_wprod1<<<IN_F + 1, HID_F>>>(W1, W2, b1);
    k_wprod2<<<IN_F + 1, OUT_F>>>(W3, b2);

    // fused GEMM + pooling (f32x2)
    dim3 gemm_grid((N_NODES + BM - 1) / BM, OUT_F / BN);
    k_gemm_pool<<<gemm_grid, 256>>>(b3, batch);

    k_out<<<NUM_GRAPHS, 2 * OUT_F>>>(out);
}

// round 8
// speedup vs baseline: 1.0559x; 1.0559x over previous
#include <cuda_runtime.h>
#include <cuda_fp16.h>
#include <math.h>

#define N_NODES 50000
#define N_EDGES 800000
#define NUM_GRAPHS 64
#define IN_F 128
#define HID_F 256
#define OUT_F 256

#define SCAN_B 1024
#define SCAN_NBLK ((N_NODES + SCAN_B - 1) / SCAN_B)   // 49

// ---------------- scratch (static device globals) ----------------
__device__ int   g_degi[N_NODES];
__device__ int   g_row[N_NODES];
__device__ int   g_rowtmp[N_NODES];
__device__ int   g_cursor[N_NODES];
__device__ int   g_bsum[SCAN_NBLK];
__device__ int   g_boff[SCAN_NBLK];
__device__ __align__(8) int2 g_cpair[N_EDGES];   // {src, __float_as_int(norm)}
__device__ float g_dinv[N_NODES];
__device__ float g_sacc[N_NODES];
__device__ float g_s[N_NODES];
__device__ float g_t[N_NODES];
__device__ __align__(16) __half g_yA[(size_t)N_NODES * IN_F];
__device__ __align__(16) __half g_yB[(size_t)N_NODES * IN_F];
__device__ float g_T1[IN_F * HID_F];
__device__ float g_M[IN_F * OUT_F];
__device__ float g_u1[HID_F];
__device__ float g_u[OUT_F];
__device__ float g_w[OUT_F];
__device__ unsigned g_pmax[NUM_GRAPHS * OUT_F];
__device__ float g_psum[NUM_GRAPHS * OUT_F];
__device__ float g_cnt[NUM_GRAPHS];

// ---------------- helpers ----------------
__device__ __forceinline__ unsigned enc_f32(float f) {
    unsigned u = __float_as_uint(f);
    return (u & 0x80000000u) ? ~u : (u | 0x80000000u);
}
__device__ __forceinline__ float dec_f32(unsigned u) {
    return (u & 0x80000000u) ? __uint_as_float(u & 0x7FFFFFFFu) : __uint_as_float(~u);
}

// ---------------- init (merged) ----------------
__global__ void k_init() {
    int i = blockIdx.x * blockDim.x + threadIdx.x;
    if (i < N_NODES) {
        g_degi[i] = 0;
        g_cursor[i] = 0;
        g_sacc[i] = 0.0f;
    }
    if (i < NUM_GRAPHS * OUT_F) {
        g_pmax[i] = 0x007FFFFFu;  // enc(-inf)
        g_psum[i] = 0.0f;
    }
    if (i < NUM_GRAPHS) g_cnt[i] = 0.0f;
}

// ---------------- CSR build (edge_index int32, layout [2, E]) ----------------
__global__ void k_deg(const int* __restrict__ ei) {
    int e = blockIdx.x * blockDim.x + threadIdx.x;
    if (e < N_EDGES) atomicAdd(&g_degi[ei[N_EDGES + e]], 1);
}

__global__ void k_scan1() {
    __shared__ int sm[SCAN_B];
    int t = threadIdx.x;
    int i = blockIdx.x * SCAN_B + t;
    int v = (i < N_NODES) ? g_degi[i] : 0;
    sm[t] = v;
    __syncthreads();
#pragma unroll
    for (int off = 1; off < SCAN_B; off <<= 1) {
        int a = (t >= off) ? sm[t - off] : 0;
        __syncthreads();
        sm[t] += a;
        __syncthreads();
    }
    if (i < N_NODES) g_rowtmp[i] = sm[t] - v;
    if (t == SCAN_B - 1) g_bsum[blockIdx.x] = sm[t];
}

__global__ void k_scan2() {
    if (threadIdx.x == 0) {
        int run = 0;
        for (int b = 0; b < SCAN_NBLK; b++) { g_boff[b] = run; run += g_bsum[b]; }
    }
}

__global__ void k_scan3() {
    int i = blockIdx.x * blockDim.x + threadIdx.x;
    if (i < N_NODES) {
        g_row[i] = g_rowtmp[i] + g_boff[i >> 10];
        g_dinv[i] = rsqrtf((float)(g_degi[i] + 1));
    }
}

__global__ void k_fill(const int* __restrict__ ei) {
    int e = blockIdx.x * blockDim.x + threadIdx.x;
    if (e < N_EDGES) {
        int s = ei[e];
        int d = ei[N_EDGES + e];
        float w = g_dinv[s] * g_dinv[d];
        int pos = g_row[d] + atomicAdd(&g_cursor[d], 1);
        g_cpair[pos] = make_int2(s, __float_as_int(w));
        atomicAdd(&g_sacc[d], w);
    }
}

__global__ void k_sfin_cnt(const int* __restrict__ batch) {
    int i = blockIdx.x * blockDim.x + threadIdx.x;
    if (i < N_NODES) {
        float di = g_dinv[i];
        g_s[i] = g_sacc[i] + di * di;
        atomicAdd(&g_cnt[batch[i]], 1.0f);
    }
}

__global__ void k_t() {
    int i = blockIdx.x * blockDim.x + threadIdx.x;
    if (i >= N_NODES) return;
    int beg = g_row[i], end = beg + g_degi[i];
    float acc = 0.f;
    for (int k = beg; k < end; k++) {
        int2 p = g_cpair[k];
        acc += __int_as_float(p.y) * g_s[p.x];
    }
    float di = g_dinv[i];
    g_t[i] = acc + di * di * g_s[i];
}

// ---------------- aggregation pass 0: fp32 x -> fp16 yA ----------------
// One warp per dst node; lane handles 4 features.
__global__ void __launch_bounds__(256) k_agg0(const float* __restrict__ x) {
    int node = (blockIdx.x * blockDim.x + threadIdx.x) >> 5;
    int lane = threadIdx.x & 31;
    if (node >= N_NODES) return;
    int beg = g_row[node], end = beg + g_degi[node];
    float di = g_dinv[node];
    float d2 = di * di;

    float4 self = *((const float4*)(x + (size_t)node * IN_F) + lane);
    float4 a0 = make_float4(d2 * self.x, d2 * self.y, d2 * self.z, d2 * self.w);
    float4 a1 = make_float4(0.f, 0.f, 0.f, 0.f);
    float4 a2 = make_float4(0.f, 0.f, 0.f, 0.f);
    float4 a3 = make_float4(0.f, 0.f, 0.f, 0.f);

    int k = beg;
    for (; k + 3 < end; k += 4) {
        int2 p0 = g_cpair[k];
        int2 p1 = g_cpair[k + 1];
        int2 p2 = g_cpair[k + 2];
        int2 p3 = g_cpair[k + 3];
        float n0 = __int_as_float(p0.y), n1 = __int_as_float(p1.y);
        float n2 = __int_as_float(p2.y), n3 = __int_as_float(p3.y);
        float4 v0 = *((const float4*)(x + (size_t)p0.x * IN_F) + lane);
        float4 v1 = *((const float4*)(x + (size_t)p1.x * IN_F) + lane);
        float4 v2 = *((const float4*)(x + (size_t)p2.x * IN_F) + lane);
        float4 v3 = *((const float4*)(x + (size_t)p3.x * IN_F) + lane);
        a0.x += n0 * v0.x; a0.y += n0 * v0.y; a0.z += n0 * v0.z; a0.w += n0 * v0.w;
        a1.x += n1 * v1.x; a1.y += n1 * v1.y; a1.z += n1 * v1.z; a1.w += n1 * v1.w;
        a2.x += n2 * v2.x; a2.y += n2 * v2.y; a2.z += n2 * v2.z; a2.w += n2 * v2.w;
        a3.x += n3 * v3.x; a3.y += n3 * v3.y; a3.z += n3 * v3.z; a3.w += n3 * v3.w;
    }
    for (; k < end; k++) {
        int2 p0 = g_cpair[k];
        float n0 = __int_as_float(p0.y);
        float4 v0 = *((const float4*)(x + (size_t)p0.x * IN_F) + lane);
        a0.x += n0 * v0.x; a0.y += n0 * v0.y; a0.z += n0 * v0.z; a0.w += n0 * v0.w;
    }
    a0.x += a1.x + a2.x + a3.x;
    a0.y += a1.y + a2.y + a3.y;
    a0.z += a1.z + a2.z + a3.z;
    a0.w += a1.w + a2.w + a3.w;

    __half2 o0 = __floats2half2_rn(a0.x, a0.y);
    __half2 o1 = __floats2half2_rn(a0.z, a0.w);
    uint2 st;
    st.x = *(unsigned*)&o0;
    st.y = *(unsigned*)&o1;
    *((uint2*)(g_yA + (size_t)node * IN_F) + lane) = st;
}

// ---------------- aggregation passes 1,2: fp16 -> fp16 ----------------
__device__ __forceinline__ float4 ld_h4(const __half* base, size_t node, int lane) {
    uint2 raw = *((const uint2*)(base + node * IN_F) + lane);
    __half2 h0 = *(__half2*)&raw.x;
    __half2 h1 = *(__half2*)&raw.y;
    float2 f0 = __half22float2(h0);
    float2 f1 = __half22float2(h1);
    return make_float4(f0.x, f0.y, f1.x, f1.y);
}

__global__ void __launch_bounds__(256) k_aggh(int pass) {
    const __half* yin = (pass == 1) ? g_yA : g_yB;
    __half* yout = (pass == 1) ? g_yB : g_yA;
    int node = (blockIdx.x * blockDim.x + threadIdx.x) >> 5;
    int lane = threadIdx.x & 31;
    if (node >= N_NODES) return;
    int beg = g_row[node], end = beg + g_degi[node];
    float di = g_dinv[node];
    float d2 = di * di;

    float4 self = ld_h4(yin, (size_t)node, lane);
    float4 a0 = make_float4(d2 * self.x, d2 * self.y, d2 * self.z, d2 * self.w);
    float4 a1 = make_float4(0.f, 0.f, 0.f, 0.f);
    float4 a2 = make_float4(0.f, 0.f, 0.f, 0.f);
    float4 a3 = make_float4(0.f, 0.f, 0.f, 0.f);

    int k = beg;
    for (; k + 3 < end; k += 4) {
        int2 p0 = g_cpair[k];
        int2 p1 = g_cpair[k + 1];
        int2 p2 = g_cpair[k + 2];
        int2 p3 = g_cpair[k + 3];
        float n0 = __int_as_float(p0.y), n1 = __int_as_float(p1.y);
        float n2 = __int_as_float(p2.y), n3 = __int_as_float(p3.y);
        float4 v0 = ld_h4(yin, (size_t)p0.x, lane);
        float4 v1 = ld_h4(yin, (size_t)p1.x, lane);
        float4 v2 = ld_h4(yin, (size_t)p2.x, lane);
        float4 v3 = ld_h4(yin, (size_t)p3.x, lane);
        a0.x += n0 * v0.x; a0.y += n0 * v0.y; a0.z += n0 * v0.z; a0.w += n0 * v0.w;
        a1.x += n1 * v1.x; a1.y += n1 * v1.y; a1.z += n1 * v1.z; a1.w += n1 * v1.w;
        a2.x += n2 * v2.x; a2.y += n2 * v2.y; a2.z += n2 * v2.z; a2.w += n2 * v2.w;
        a3.x += n3 * v3.x; a3.y += n3 * v3.y; a3.z += n3 * v3.z; a3.w += n3 * v3.w;
    }
    for (; k < end; k++) {
        int2 p0 = g_cpair[k];
        float n0 = __int_as_float(p0.y);
        float4 v0 = ld_h4(yin, (size_t)p0.x, lane);
        a0.x += n0 * v0.x; a0.y += n0 * v0.y; a0.z += n0 * v0.z; a0.w += n0 * v0.w;
    }
    a0.x += a1.x + a2.x + a3.x;
    a0.y += a1.y + a2.y + a3.y;
    a0.z += a1.z + a2.z + a3.z;
    a0.w += a1.w + a2.w + a3.w;

    __half2 o0 = __floats2half2_rn(a0.x, a0.y);
    __half2 o1 = __floats2half2_rn(a0.z, a0.w);
    uint2 st;
    st.x = *(unsigned*)&o0;
    st.y = *(unsigned*)&o1;
    *((uint2*)(yout + (size_t)node * IN_F) + lane) = st;
}

// ---------------- small weight products ----------------
__global__ void k_wprod1(const float* __restrict__ W1, const float* __restrict__ W2,
                         const float* __restrict__ b1) {
    int j = threadIdx.x;
    int i = blockIdx.x;
    if (i < IN_F) {
        float acc = 0.f;
        for (int k = 0; k < HID_F; k++) acc += W1[i * HID_F + k] * W2[k * HID_F + j];
        g_T1[i * HID_F + j] = acc;
    } else {
        float acc = 0.f;
        for (int k = 0; k < HID_F; k++) acc += b1[k] * W2[k * HID_F + j];
        g_u1[j] = acc;
    }
}

__global__ void k_wprod2(const float* __restrict__ W3, const float* __restrict__ b2) {
    int j = threadIdx.x;
    int i = blockIdx.x;
    if (i < IN_F) {
        float acc = 0.f;
        for (int k = 0; k < HID_F; k++) acc += g_T1[i * HID_F + k] * W3[k * OUT_F + j];
        g_M[i * OUT_F + j] = acc;
    } else {
        float a = 0.f, b = 0.f;
        for (int k = 0; k < HID_F; k++) {
            float w3 = W3[k * OUT_F + j];
            a += g_u1[k] * w3;
            b += b2[k] * w3;
        }
        g_u[j] = a;
        g_w[j] = b;
    }
}

// ---------------- fused GEMM + pooling (A in fp16, scalar FFMA mainloop) ----------------
#define BM 128
#define BN 128
#define BK 32
__global__ void __launch_bounds__(256) k_gemm_pool(const float* __restrict__ b3,
                                                   const int* __restrict__ batch) {
    __shared__ float As[BM][BK + 1];
    __shared__ float Bs[BK][BN + 4];
    const __half* Ah = g_yA;   // y3 lives in g_yA after 3 passes
    const float* B = g_M;
    int bx = blockIdx.y;
    int row0 = blockIdx.x * BM;
    int tid = threadIdx.x;
    int tx = tid & 15, ty = tid >> 4;
    float acc[8][8];
#pragma unroll
    for (int i = 0; i < 8; i++)
#pragma unroll
        for (int j = 0; j < 8; j++) acc[i][j] = 0.f;

    for (int kb = 0; kb < IN_F; kb += BK) {
        // A tile from fp16: 512 chunks of 8 halves
#pragma unroll
        for (int i = 0; i < 2; i++) {
            int id = tid + i * 256;
            int r = id >> 2;            // row within tile (0..127)
            int c = (id & 3) * 8;       // k offset (0,8,16,24)
            float vals[8];
#pragma unroll
            for (int t = 0; t < 8; t++) vals[t] = 0.f;
            int gr = row0 + r;
            if (gr < N_NODES) {
                uint4 raw = *(const uint4*)(Ah + (size_t)gr * IN_F + kb + c);
                const __half2* hp = (const __half2*)&raw;
#pragma unroll
                for (int t = 0; t < 4; t++) {
                    float2 f = __half22float2(hp[t]);
                    vals[2 * t] = f.x;
                    vals[2 * t + 1] = f.y;
                }
            }
#pragma unroll
            for (int t = 0; t < 8; t++) As[r][c + t] = vals[t];
        }
#pragma unroll
        for (int i = 0; i < 4; i++) {
            int id = tid + i * 256;
            int kr = id >> 5;
            int c = (id & 31) * 4;
            float4 v = *(const float4*)(B + (size_t)(kb + kr) * OUT_F + bx * BN + c);
            Bs[kr][c] = v.x; Bs[kr][c + 1] = v.y; Bs[kr][c + 2] = v.z; Bs[kr][c + 3] = v.w;
        }
        __syncthreads();
#pragma unroll
        for (int k = 0; k < BK; k++) {
            float ra[8], rb[8];
#pragma unroll
            for (int i = 0; i < 8; i++) ra[i] = As[ty * 8 + i][k];
#pragma unroll
            for (int j = 0; j < 8; j++) rb[j] = Bs[k][tx * 8 + j];
#pragma unroll
            for (int i = 0; i < 8; i++)
#pragma unroll
                for (int j = 0; j < 8; j++) acc[i][j] += ra[i] * rb[j];
        }
        __syncthreads();
    }

    // epilogue: rank-1 terms + bias, then pooled reduction (batch is sorted)
    float uj[8], wj[8], bj[8];
    int gc0 = bx * BN + tx * 8;
#pragma unroll
    for (int j = 0; j < 8; j++) {
        uj[j] = g_u[gc0 + j];
        wj[j] = g_w[gc0 + j];
        bj[j] = b3[gc0 + j];
    }

    int curg = -1;
    float rmax[8], rsum[8];
#pragma unroll
    for (int i = 0; i < 8; i++) {
        int gr = row0 + ty * 8 + i;
        if (gr < N_NODES) {
            int g = batch[gr];
            float tr = g_t[gr], sr = g_s[gr];
            if (g != curg) {
                if (curg >= 0) {
#pragma unroll
                    for (int j = 0; j < 8; j++) {
                        atomicMax(&g_pmax[curg * OUT_F + gc0 + j], enc_f32(rmax[j]));
                        atomicAdd(&g_psum[curg * OUT_F + gc0 + j], rsum[j]);
                    }
                }
                curg = g;
#pragma unroll
                for (int j = 0; j < 8; j++) { rmax[j] = -INFINITY; rsum[j] = 0.f; }
            }
#pragma unroll
            for (int j = 0; j < 8; j++) {
                float h = acc[i][j] + tr * uj[j] + sr * wj[j] + bj[j];
                rmax[j] = fmaxf(rmax[j], h);
                rsum[j] += h;
            }
        }
    }
    if (curg >= 0) {
#pragma unroll
        for (int j = 0; j < 8; j++) {
            atomicMax(&g_pmax[curg * OUT_F + gc0 + j], enc_f32(rmax[j]));
            atomicAdd(&g_psum[curg * OUT_F + gc0 + j], rsum[j]);
        }
    }
}

__global__ void k_out(float* __restrict__ out) {
    int g = blockIdx.x;
    int c = threadIdx.x;                   // 512 threads
    if (c < OUT_F) {
        out[g * 2 * OUT_F + c] = dec_f32(g_pmax[g * OUT_F + c]);
    } else {
        int cc = c - OUT_F;
        float cnt = g_cnt[g];
        out[g * 2 * OUT_F + OUT_F + cc] = g_psum[g * OUT_F + cc] / fmaxf(cnt, 1.0f);
    }
}

// ---------------- launch ----------------
extern "C" void kernel_launch(void* const* d_in, const int* in_sizes, int n_in,
                              void* d_out, int out_size) {
    const float* x = (const float*)d_in[0];
    const int* ei = (const int*)d_in[1];       // int32 (JAX x64 disabled)
    const int* batch = (const int*)d_in[2];    // int32
    const float* W1 = (const float*)d_in[3];
    const float* b1 = (const float*)d_in[4];
    const float* W2 = (const float*)d_in[5];
    const float* b2 = (const float*)d_in[6];
    const float* W3 = (const float*)d_in[7];
    const float* b3 = (const float*)d_in[8];
    float* out = (float*)d_out;

    const int NT = 256;
    int nb_nodes = (N_NODES + NT - 1) / NT;
    int nb_edges = (N_EDGES + NT - 1) / NT;
    int nb_aggw  = (N_NODES * 32 + NT - 1) / NT;     // one warp per node

    // CSR build
    k_init<<<nb_nodes, NT>>>();
    k_deg<<<nb_edges, NT>>>(ei);
    k_scan1<<<SCAN_NBLK, SCAN_B>>>();
    k_scan2<<<1, 32>>>();
    k_scan3<<<nb_nodes, NT>>>();
    k_fill<<<nb_edges, NT>>>(ei);

    // scalar propagations
    k_sfin_cnt<<<nb_nodes, NT>>>(batch);
    k_t<<<nb_nodes, NT>>>();

    // three aggregation passes at width 128 (gather; fp16 intermediates)
    k_agg0<<<nb_aggw, NT>>>(x);
    k_aggh<<<nb_aggw, NT>>>(1);
    k_aggh<<<nb_aggw, NT>>>(2);

    // weight pre-products (tiny)
    k_wprod1<<<IN_F + 1, HID_F>>>(W1, W2, b1);
    k_wprod2<<<IN_F + 1, OUT_F>>>(W3, b2);

    // fused GEMM + pooling
    dim3 gemm_grid((N_NODES + BM - 1) / BM, OUT_F / BN);
    k_gemm_pool<<<gemm_grid, 256>>>(b3, batch);

    k_out<<<NUM_GRAPHS, 2 * OUT_F>>>(out);
}

// round 9
// speedup vs baseline: 1.2323x; 1.1671x over previous
#include <cuda_runtime.h>
#include <cuda_fp16.h>
#include <mma.h>
#include <math.h>

using namespace nvcuda;

#define N_NODES 50000
#define N_PAD 50048            // padded to multiple of 128 for tensor-core tiles
#define N_EDGES 800000
#define NUM_GRAPHS 64
#define IN_F 128
#define HID_F 256
#define OUT_F 256

#define SCAN_B 1024
#define SCAN_NBLK ((N_NODES + SCAN_B - 1) / SCAN_B)   // 49

// ---------------- scratch (static device globals) ----------------
__device__ int   g_degi[N_NODES];
__device__ int   g_row[N_NODES];
__device__ int   g_rowtmp[N_NODES];
__device__ int   g_cursor[N_NODES];
__device__ int   g_bsum[SCAN_NBLK];
__device__ int   g_boff[SCAN_NBLK];
__device__ __align__(8) int2 g_cpair[N_EDGES];   // {src, __float_as_int(norm)}
__device__ float g_dinv[N_NODES];
__device__ float g_sacc[N_NODES];
__device__ float g_s[N_NODES];
__device__ float g_t[N_NODES];
__device__ __align__(16) __half g_yA[(size_t)N_PAD * IN_F];
__device__ __align__(16) __half g_yB[(size_t)N_PAD * IN_F];
__device__ float g_T1[IN_F * HID_F];
__device__ __align__(16) __half g_Mh[IN_F * OUT_F];   // fp16 composite weight
__device__ float g_u1[HID_F];
__device__ float g_u[OUT_F];
__device__ float g_w[OUT_F];
__device__ unsigned g_pmax[NUM_GRAPHS * OUT_F];
__device__ float g_psum[NUM_GRAPHS * OUT_F];
__device__ float g_cnt[NUM_GRAPHS];

// ---------------- helpers ----------------
__device__ __forceinline__ unsigned enc_f32(float f) {
    unsigned u = __float_as_uint(f);
    return (u & 0x80000000u) ? ~u : (u | 0x80000000u);
}
__device__ __forceinline__ float dec_f32(unsigned u) {
    return (u & 0x80000000u) ? __uint_as_float(u & 0x7FFFFFFFu) : __uint_as_float(~u);
}

// ---------------- init (merged) ----------------
__global__ void k_init() {
    int i = blockIdx.x * blockDim.x + threadIdx.x;
    if (i < N_NODES) {
        g_degi[i] = 0;
        g_cursor[i] = 0;
        g_sacc[i] = 0.0f;
    }
    if (i < NUM_GRAPHS * OUT_F) {
        g_pmax[i] = 0x007FFFFFu;  // enc(-inf)
        g_psum[i] = 0.0f;
    }
    if (i < NUM_GRAPHS) g_cnt[i] = 0.0f;
}

// zero the pad rows of g_yA once so tensor tiles read clean data
__global__ void k_padzero() {
    int i = blockIdx.x * blockDim.x + threadIdx.x;
    int total = (N_PAD - N_NODES) * IN_F / 2;   // half2 count
    if (i < total) {
        ((__half2*)(g_yA + (size_t)N_NODES * IN_F))[i] = __half2half2(__float2half(0.f));
    }
}

// ---------------- CSR build (edge_index int32, layout [2, E]) ----------------
__global__ void k_deg(const int* __restrict__ ei) {
    int e = blockIdx.x * blockDim.x + threadIdx.x;
    if (e < N_EDGES) atomicAdd(&g_degi[ei[N_EDGES + e]], 1);
}

__global__ void k_scan1() {
    __shared__ int sm[SCAN_B];
    int t = threadIdx.x;
    int i = blockIdx.x * SCAN_B + t;
    int v = (i < N_NODES) ? g_degi[i] : 0;
    sm[t] = v;
    __syncthreads();
#pragma unroll
    for (int off = 1; off < SCAN_B; off <<= 1) {
        int a = (t >= off) ? sm[t - off] : 0;
        __syncthreads();
        sm[t] += a;
        __syncthreads();
    }
    if (i < N_NODES) g_rowtmp[i] = sm[t] - v;
    if (t == SCAN_B - 1) g_bsum[blockIdx.x] = sm[t];
}

__global__ void k_scan2() {
    if (threadIdx.x == 0) {
        int run = 0;
        for (int b = 0; b < SCAN_NBLK; b++) { g_boff[b] = run; run += g_bsum[b]; }
    }
}

__global__ void k_scan3() {
    int i = blockIdx.x * blockDim.x + threadIdx.x;
    if (i < N_NODES) {
        g_row[i] = g_rowtmp[i] + g_boff[i >> 10];
        g_dinv[i] = rsqrtf((float)(g_degi[i] + 1));
    }
}

__global__ void k_fill(const int* __restrict__ ei) {
    int e = blockIdx.x * blockDim.x + threadIdx.x;
    if (e < N_EDGES) {
        int s = ei[e];
        int d = ei[N_EDGES + e];
        float w = g_dinv[s] * g_dinv[d];
        int pos = g_row[d] + atomicAdd(&g_cursor[d], 1);
        g_cpair[pos] = make_int2(s, __float_as_int(w));
        atomicAdd(&g_sacc[d], w);
    }
}

__global__ void k_sfin_cnt(const int* __restrict__ batch) {
    int i = blockIdx.x * blockDim.x + threadIdx.x;
    if (i < N_NODES) {
        float di = g_dinv[i];
        g_s[i] = g_sacc[i] + di * di;
        atomicAdd(&g_cnt[batch[i]], 1.0f);
    }
}

__global__ void k_t() {
    int i = blockIdx.x * blockDim.x + threadIdx.x;
    if (i >= N_NODES) return;
    int beg = g_row[i], end = beg + g_degi[i];
    float acc = 0.f;
    for (int k = beg; k < end; k++) {
        int2 p = g_cpair[k];
        acc += __int_as_float(p.y) * g_s[p.x];
    }
    float di = g_dinv[i];
    g_t[i] = acc + di * di * g_s[i];
}

// ---------------- aggregation pass 0: fp32 x -> fp16 yA ----------------
__global__ void __launch_bounds__(256) k_agg0(const float* __restrict__ x) {
    int node = (blockIdx.x * blockDim.x + threadIdx.x) >> 5;
    int lane = threadIdx.x & 31;
    if (node >= N_NODES) return;
    int beg = g_row[node], end = beg + g_degi[node];
    float di = g_dinv[node];
    float d2 = di * di;

    float4 self = *((const float4*)(x + (size_t)node * IN_F) + lane);
    float4 a0 = make_float4(d2 * self.x, d2 * self.y, d2 * self.z, d2 * self.w);
    float4 a1 = make_float4(0.f, 0.f, 0.f, 0.f);
    float4 a2 = make_float4(0.f, 0.f, 0.f, 0.f);
    float4 a3 = make_float4(0.f, 0.f, 0.f, 0.f);

    int k = beg;
    for (; k + 3 < end; k += 4) {
        int2 p0 = g_cpair[k];
        int2 p1 = g_cpair[k + 1];
        int2 p2 = g_cpair[k + 2];
        int2 p3 = g_cpair[k + 3];
        float n0 = __int_as_float(p0.y), n1 = __int_as_float(p1.y);
        float n2 = __int_as_float(p2.y), n3 = __int_as_float(p3.y);
        float4 v0 = *((const float4*)(x + (size_t)p0.x * IN_F) + lane);
        float4 v1 = *((const float4*)(x + (size_t)p1.x * IN_F) + lane);
        float4 v2 = *((const float4*)(x + (size_t)p2.x * IN_F) + lane);
        float4 v3 = *((const float4*)(x + (size_t)p3.x * IN_F) + lane);
        a0.x += n0 * v0.x; a0.y += n0 * v0.y; a0.z += n0 * v0.z; a0.w += n0 * v0.w;
        a1.x += n1 * v1.x; a1.y += n1 * v1.y; a1.z += n1 * v1.z; a1.w += n1 * v1.w;
        a2.x += n2 * v2.x; a2.y += n2 * v2.y; a2.z += n2 * v2.z; a2.w += n2 * v2.w;
        a3.x += n3 * v3.x; a3.y += n3 * v3.y; a3.z += n3 * v3.z; a3.w += n3 * v3.w;
    }
    for (; k < end; k++) {
        int2 p0 = g_cpair[k];
        float n0 = __int_as_float(p0.y);
        float4 v0 = *((const float4*)(x + (size_t)p0.x * IN_F) + lane);
        a0.x += n0 * v0.x; a0.y += n0 * v0.y; a0.z += n0 * v0.z; a0.w += n0 * v0.w;
    }
    a0.x += a1.x + a2.x + a3.x;
    a0.y += a1.y + a2.y + a3.y;
    a0.z += a1.z + a2.z + a3.z;
    a0.w += a1.w + a2.w + a3.w;

    __half2 o0 = __floats2half2_rn(a0.x, a0.y);
    __half2 o1 = __floats2half2_rn(a0.z, a0.w);
    uint2 st;
    st.x = *(unsigned*)&o0;
    st.y = *(unsigned*)&o1;
    *((uint2*)(g_yA + (size_t)node * IN_F) + lane) = st;
}

// ---------------- aggregation passes 1,2: fp16 -> fp16 ----------------
__device__ __forceinline__ float4 ld_h4(const __half* base, size_t node, int lane) {
    uint2 raw = *((const uint2*)(base + node * IN_F) + lane);
    __half2 h0 = *(__half2*)&raw.x;
    __half2 h1 = *(__half2*)&raw.y;
    float2 f0 = __half22float2(h0);
    float2 f1 = __half22float2(h1);
    return make_float4(f0.x, f0.y, f1.x, f1.y);
}

__global__ void __launch_bounds__(256) k_aggh(int pass) {
    const __half* yin = (pass == 1) ? g_yA : g_yB;
    __half* yout = (pass == 1) ? g_yB : g_yA;
    int node = (blockIdx.x * blockDim.x + threadIdx.x) >> 5;
    int lane = threadIdx.x & 31;
    if (node >= N_NODES) return;
    int beg = g_row[node], end = beg + g_degi[node];
    float di = g_dinv[node];
    float d2 = di * di;

    float4 self = ld_h4(yin, (size_t)node, lane);
    float4 a0 = make_float4(d2 * self.x, d2 * self.y, d2 * self.z, d2 * self.w);
    float4 a1 = make_float4(0.f, 0.f, 0.f, 0.f);
    float4 a2 = make_float4(0.f, 0.f, 0.f, 0.f);
    float4 a3 = make_float4(0.f, 0.f, 0.f, 0.f);

    int k = beg;
    for (; k + 3 < end; k += 4) {
        int2 p0 = g_cpair[k];
        int2 p1 = g_cpair[k + 1];
        int2 p2 = g_cpair[k + 2];
        int2 p3 = g_cpair[k + 3];
        float n0 = __int_as_float(p0.y), n1 = __int_as_float(p1.y);
        float n2 = __int_as_float(p2.y), n3 = __int_as_float(p3.y);
        float4 v0 = ld_h4(yin, (size_t)p0.x, lane);
        float4 v1 = ld_h4(yin, (size_t)p1.x, lane);
        float4 v2 = ld_h4(yin, (size_t)p2.x, lane);
        float4 v3 = ld_h4(yin, (size_t)p3.x, lane);
        a0.x += n0 * v0.x; a0.y += n0 * v0.y; a0.z += n0 * v0.z; a0.w += n0 * v0.w;
        a1.x += n1 * v1.x; a1.y += n1 * v1.y; a1.z += n1 * v1.z; a1.w += n1 * v1.w;
        a2.x += n2 * v2.x; a2.y += n2 * v2.y; a2.z += n2 * v2.z; a2.w += n2 * v2.w;
        a3.x += n3 * v3.x; a3.y += n3 * v3.y; a3.z += n3 * v3.z; a3.w += n3 * v3.w;
    }
    for (; k < end; k++) {
        int2 p0 = g_cpair[k];
        float n0 = __int_as_float(p0.y);
        float4 v0 = ld_h4(yin, (size_t)p0.x, lane);
        a0.x += n0 * v0.x; a0.y += n0 * v0.y; a0.z += n0 * v0.z; a0.w += n0 * v0.w;
    }
    a0.x += a1.x + a2.x + a3.x;
    a0.y += a1.y + a2.y + a3.y;
    a0.z += a1.z + a2.z + a3.z;
    a0.w += a1.w + a2.w + a3.w;

    __half2 o0 = __floats2half2_rn(a0.x, a0.y);
    __half2 o1 = __floats2half2_rn(a0.z, a0.w);
    uint2 st;
    st.x = *(unsigned*)&o0;
    st.y = *(unsigned*)&o1;
    *((uint2*)(yout + (size_t)node * IN_F) + lane) = st;
}

// ---------------- small weight products ----------------
__global__ void k_wprod1(const float* __restrict__ W1, const float* __restrict__ W2,
                         const float* __restrict__ b1) {
    int j = threadIdx.x;
    int i = blockIdx.x;
    if (i < IN_F) {
        float acc = 0.f;
        for (int k = 0; k < HID_F; k++) acc += W1[i * HID_F + k] * W2[k * HID_F + j];
        g_T1[i * HID_F + j] = acc;
    } else {
        float acc = 0.f;
        for (int k = 0; k < HID_F; k++) acc += b1[k] * W2[k * HID_F + j];
        g_u1[j] = acc;
    }
}

__global__ void k_wprod2(const float* __restrict__ W3, const float* __restrict__ b2) {
    int j = threadIdx.x;
    int i = blockIdx.x;
    if (i < IN_F) {
        float acc = 0.f;
        for (int k = 0; k < HID_F; k++) acc += g_T1[i * HID_F + k] * W3[k * OUT_F + j];
        g_Mh[i * OUT_F + j] = __float2half_rn(acc);
    } else {
        float a = 0.f, b = 0.f;
        for (int k = 0; k < HID_F; k++) {
            float w3 = W3[k * OUT_F + j];
            a += g_u1[k] * w3;
            b += b2[k] * w3;
        }
        g_u[j] = a;
        g_w[j] = b;
    }
}

// ---------------- tensor-core GEMM + fused pooling ----------------
// h = y3 @ Mh + t*u^T + s*w^T + b3, pooled into g_pmax / g_psum.
// Block tile: 128 rows x 64 cols; 8 warps = 4 row-groups x 2 col-groups.
#define GBM 128
#define GBN 64
#define CS_LD (GBN + 4)
__global__ void __launch_bounds__(256) k_gemm_pool(const float* __restrict__ b3,
                                                   const int* __restrict__ batch) {
    __shared__ float Cs[GBM][CS_LD];
    int warp = threadIdx.x >> 5;
    int wr = warp >> 1;           // 0..3  (32-row group)
    int wc = warp & 1;            // 0..1  (32-col group)
    int row0 = blockIdx.x * GBM;
    int col0 = blockIdx.y * GBN;

    wmma::fragment<wmma::accumulator, 16, 16, 16, float> acc[2][2];
#pragma unroll
    for (int i = 0; i < 2; i++)
#pragma unroll
        for (int j = 0; j < 2; j++) wmma::fill_fragment(acc[i][j], 0.0f);

    const __half* Abase = g_yA + (size_t)(row0 + wr * 32) * IN_F;
    const __half* Bbase = g_Mh + col0 + wc * 32;

#pragma unroll
    for (int k = 0; k < IN_F; k += 16) {
        wmma::fragment<wmma::matrix_a, 16, 16, 16, __half, wmma::row_major> af[2];
        wmma::fragment<wmma::matrix_b, 16, 16, 16, __half, wmma::row_major> bf[2];
        wmma::load_matrix_sync(af[0], Abase + k, IN_F);
        wmma::load_matrix_sync(af[1], Abase + 16 * IN_F + k, IN_F);
        wmma::load_matrix_sync(bf[0], Bbase + (size_t)k * OUT_F, OUT_F);
        wmma::load_matrix_sync(bf[1], Bbase + (size_t)k * OUT_F + 16, OUT_F);
#pragma unroll
        for (int i = 0; i < 2; i++)
#pragma unroll
            for (int j = 0; j < 2; j++)
                wmma::mma_sync(acc[i][j], af[i], bf[j], acc[i][j]);
    }

#pragma unroll
    for (int i = 0; i < 2; i++)
#pragma unroll
        for (int j = 0; j < 2; j++)
            wmma::store_matrix_sync(&Cs[wr * 32 + i * 16][wc * 32 + j * 16],
                                    acc[i][j], CS_LD, wmma::mem_row_major);
    __syncthreads();

    // pooling epilogue: 256 threads = 64 cols x 4 row-chunks of 32
    int c = threadIdx.x & 63;
    int r0 = (threadIdx.x >> 6) * 32;
    int gc = col0 + c;
    float u = g_u[gc], w = g_w[gc], b = b3[gc];

    int curg = -1;
    float rmax = -INFINITY, rsum = 0.f;
    for (int r = r0; r < r0 + 32; r++) {
        int gr = row0 + r;
        if (gr >= N_NODES) break;
        int g = batch[gr];
        if (g != curg) {
            if (curg >= 0) {
                atomicMax(&g_pmax[curg * OUT_F + gc], enc_f32(rmax));
                atomicAdd(&g_psum[curg * OUT_F + gc], rsum);
            }
            curg = g; rmax = -INFINITY; rsum = 0.f;
        }
        float h = Cs[r][c] + g_t[gr] * u + g_s[gr] * w + b;
        rmax = fmaxf(rmax, h);
        rsum += h;
    }
    if (curg >= 0) {
        atomicMax(&g_pmax[curg * OUT_F + gc], enc_f32(rmax));
        atomicAdd(&g_psum[curg * OUT_F + gc], rsum);
    }
}

__global__ void k_out(float* __restrict__ out) {
    int g = blockIdx.x;
    int c = threadIdx.x;                   // 512 threads
    if (c < OUT_F) {
        out[g * 2 * OUT_F + c] = dec_f32(g_pmax[g * OUT_F + c]);
    } else {
        int cc = c - OUT_F;
        float cnt = g_cnt[g];
        out[g * 2 * OUT_F + OUT_F + cc] = g_psum[g * OUT_F + cc] / fmaxf(cnt, 1.0f);
    }
}

// ---------------- launch ----------------
extern "C" void kernel_launch(void* const* d_in, const int* in_sizes, int n_in,
                              void* d_out, int out_size) {
    const float* x = (const float*)d_in[0];
    const int* ei = (const int*)d_in[1];       // int32 (JAX x64 disabled)
    const int* batch = (const int*)d_in[2];    // int32
    const float* W1 = (const float*)d_in[3];
    const float* b1 = (const float*)d_in[4];
    const float* W2 = (const float*)d_in[5];
    const float* b2 = (const float*)d_in[6];
    const float* W3 = (const float*)d_in[7];
    const float* b3 = (const float*)d_in[8];
    float* out = (float*)d_out;

    const int NT = 256;
    int nb_nodes = (N_NODES + NT - 1) / NT;
    int nb_edges = (N_EDGES + NT - 1) / NT;
    int nb_aggw  = (N_NODES * 32 + NT - 1) / NT;     // one warp per node
    int nb_pad   = ((N_PAD - N_NODES) * IN_F / 2 + NT - 1) / NT;

    // CSR build
    k_init<<<nb_nodes, NT>>>();
    k_padzero<<<nb_pad, NT>>>();
    k_deg<<<nb_edges, NT>>>(ei);
    k_scan1<<<SCAN_NBLK, SCAN_B>>>();
    k_scan2<<<1, 32>>>();
    k_scan3<<<nb_nodes, NT>>>();
    k_fill<<<nb_edges, NT>>>(ei);

    // scalar propagations
    k_sfin_cnt<<<nb_nodes, NT>>>(batch);
    k_t<<<nb_nodes, NT>>>();

    // three aggregation passes at width 128 (gather; fp16 intermediates)
    k_agg0<<<nb_aggw, NT>>>(x);
    k_aggh<<<nb_aggw, NT>>>(1);
    k_aggh<<<nb_aggw, NT>>>(2);

    // weight pre-products (tiny)
    k_wprod1<<<IN_F + 1, HID_F>>>(W1, W2, b1);
    k_wprod2<<<IN_F + 1, OUT_F>>>(W3, b2);

    // tensor-core GEMM + fused pooling
    dim3 gemm_grid(N_PAD / GBM, OUT_F / GBN);
    k_gemm_pool<<<gemm_grid, 256>>>(b3, batch);

    k_out<<<NUM_GRAPHS, 2 * OUT_F>>>(out);
}